// round 17
// baseline (speedup 1.0000x reference)
#include <cuda_runtime.h>
#include <cuda_fp16.h>
#include <cstdint>

#define B_    2
#define S_    2048
#define E_    2048
#define H_    16
#define KVH_  4
#define D_    128
#define BS_   (B_*S_)          // 4096
#define NKV_  (KVH_ * D_)      // 512
#define NQKV_ (E_ + 2 * NKV_)  // 3072
#define SOFTMAX_SCALE 0.08838834764831845f   // 1/sqrt(128)

// ---------------- scratch (static device arrays; no allocation allowed) ----
__device__ __half g_Qh [BS_ * E_];          // scaled, rope'd Q hi
__device__ __half g_Ql [BS_ * E_];          // scaled, rope'd Q lo
__device__ __half g_Kh [BS_ * NKV_];        // rope'd K hi
__device__ __half g_Kl [BS_ * NKV_];        // rope'd K lo
__device__ __half g_Vh [BS_ * NKV_];        // V fp16
__device__ __half g_xh  [BS_ * E_];
__device__ __half g_wqkvh[NQKV_ * E_];
__device__ __half g_woh [E_ * E_];
__device__ __half g_AOh [BS_ * E_];

// ---------------- helpers ---------------------------------------------------
__device__ __forceinline__ uint32_t smem_u32(const void* p) {
    uint32_t a;
    asm("{ .reg .u64 t; cvta.to.shared.u64 t, %1; cvt.u32.u64 %0, t; }"
        : "=r"(a) : "l"(p));
    return a;
}
__device__ __forceinline__ void ldsm_x4(uint32_t r[4], uint32_t addr) {
    asm volatile("ldmatrix.sync.aligned.m8n8.x4.shared.b16 {%0,%1,%2,%3}, [%4];"
                 : "=r"(r[0]), "=r"(r[1]), "=r"(r[2]), "=r"(r[3]) : "r"(addr));
}
__device__ __forceinline__ void ldsm_x2(uint32_t r[2], uint32_t addr) {
    asm volatile("ldmatrix.sync.aligned.m8n8.x2.shared.b16 {%0,%1}, [%2];"
                 : "=r"(r[0]), "=r"(r[1]) : "r"(addr));
}
__device__ __forceinline__ void ldsm_x2_trans(uint32_t r[2], uint32_t addr) {
    asm volatile("ldmatrix.sync.aligned.m8n8.x2.trans.shared.b16 {%0,%1}, [%2];"
                 : "=r"(r[0]), "=r"(r[1]) : "r"(addr));
}
__device__ __forceinline__ void mma_f16(
    float* c, const uint32_t a[4], const uint32_t b[2])
{
    asm volatile(
        "mma.sync.aligned.m16n8k16.row.col.f32.f16.f16.f32 "
        "{%0,%1,%2,%3}, {%4,%5,%6,%7}, {%8,%9}, {%0,%1,%2,%3};\n"
        : "+f"(c[0]), "+f"(c[1]), "+f"(c[2]), "+f"(c[3])
        : "r"(a[0]), "r"(a[1]), "r"(a[2]), "r"(a[3]), "r"(b[0]), "r"(b[1]));
}
#define CP_ASYNC16(dst, src) \
    asm volatile("cp.async.ca.shared.global [%0], [%1], 16;" \
                 :: "r"(dst), "l"(src) : "memory")
#define CP_COMMIT() asm volatile("cp.async.commit_group;" ::: "memory")
#define CP_WAIT(n)  asm volatile("cp.async.wait_group %0;" :: "n"(n) : "memory")

// ===========================================================================
// fp32 -> fp16 bulk converts
// ===========================================================================
__global__ __launch_bounds__(256) void cvt_f32_f16(
    const float* __restrict__ src, __half* __restrict__ dst, int n)
{
    int i = (blockIdx.x * blockDim.x + threadIdx.x) * 8;
    if (i >= n) return;
    float4 a = *(const float4*)&src[i];
    float4 b = *(const float4*)&src[i + 4];
    __half2 h0 = __floats2half2_rn(a.x, a.y);
    __half2 h1 = __floats2half2_rn(a.z, a.w);
    __half2 h2 = __floats2half2_rn(b.x, b.y);
    __half2 h3 = __floats2half2_rn(b.z, b.w);
    *(uint4*)&dst[i] = make_uint4(*(uint32_t*)&h0, *(uint32_t*)&h1,
                                  *(uint32_t*)&h2, *(uint32_t*)&h3);
}

__global__ __launch_bounds__(256) void cvt3_f32_f16(
    const float* __restrict__ wq, const float* __restrict__ wk,
    const float* __restrict__ wv, __half* __restrict__ dst)
{
    int i = (blockIdx.x * blockDim.x + threadIdx.x) * 8;
    if (i >= NQKV_ * E_) return;
    const float* src;
    if (i < E_ * E_)                   src = wq + i;
    else if (i < (E_ + NKV_) * E_)     src = wk + (i - E_ * E_);
    else                               src = wv + (i - (E_ + NKV_) * E_);
    float4 a = *(const float4*)&src[0];
    float4 b = *(const float4*)&src[4];
    __half2 h0 = __floats2half2_rn(a.x, a.y);
    __half2 h1 = __floats2half2_rn(a.z, a.w);
    __half2 h2 = __floats2half2_rn(b.x, b.y);
    __half2 h3 = __floats2half2_rn(b.z, b.w);
    *(uint4*)&dst[i] = make_uint4(*(uint32_t*)&h0, *(uint32_t*)&h1,
                                  *(uint32_t*)&h2, *(uint32_t*)&h3);
}

// ===========================================================================
// GEMM core (R16 WIN config): 128x128 tile, BK=64, 8 warps (2x4),
// warp tile 64x32, cp.async 2-stage + fragment double buffering.
// ===========================================================================
#define TBM 128
#define TBN 128
#define TBK 64
#define HP  72
#define STG_HALFS (2 * TBM * HP)
#define GEMM_SMEM (2 * STG_HALFS * 2)          // 73728 B

#define GEMM_MAINLOOP(A, W, K)                                                  \
    const int tid  = threadIdx.x;                                               \
    const int lane = tid & 31;                                                  \
    const int warp = tid >> 5;                                                  \
    const int wm   = (warp & 1) * 64;                                           \
    const int wn   = (warp >> 1) * 32;                                          \
    const int gid  = lane >> 2;                                                 \
    const int tig  = lane & 3;                                                  \
    const int bm   = blockIdx.y * TBM;                                          \
    const int bn   = blockIdx.x * TBN;                                          \
    const int arow = lane & 15;                                                 \
    const int acol = (lane & 16) ? 8 : 0;                                       \
    const int brow = lane & 7;                                                  \
    const int bcol = (lane & 8) ? 8 : 0;                                        \
    float acc[4][4][4];                                                         \
    _Pragma("unroll")                                                           \
    for (int mi = 0; mi < 4; mi++)                                              \
        _Pragma("unroll")                                                       \
        for (int ni = 0; ni < 4; ni++)                                          \
            _Pragma("unroll")                                                   \
            for (int c = 0; c < 4; c++) acc[mi][ni][c] = 0.0f;                  \
    const int NC = (K) / TBK;                                                   \
    auto issue = [&](int chunk) {                                               \
        __half* sA = sh + (chunk & 1) * STG_HALFS;                              \
        __half* sB = sA + TBM * HP;                                             \
        int k0 = chunk * TBK;                                                   \
        _Pragma("unroll")                                                       \
        for (int it = 0; it < 4; it++) {                                        \
            int f = tid + it * 256, rr = f >> 3, sg = (f & 7) * 8;              \
            CP_ASYNC16(smem_u32(&sA[rr * HP + sg]),                             \
                       &(A)[(size_t)(bm + rr) * (K) + k0 + sg]);                \
            CP_ASYNC16(smem_u32(&sB[rr * HP + sg]),                             \
                       &(W)[(size_t)(bn + rr) * (K) + k0 + sg]);                \
        }                                                                       \
        CP_COMMIT();                                                            \
    };                                                                          \
    uint32_t afr[2][4][4], bfr[2][4][2];                                        \
    issue(0);                                                                   \
    if (NC > 1) issue(1);                                                       \
    for (int i = 0; i < NC; i++) {                                              \
        if (i + 1 < NC) CP_WAIT(1); else CP_WAIT(0);                            \
        __syncthreads();                                                        \
        __half* sA = sh + (i & 1) * STG_HALFS;                                  \
        __half* sB = sA + TBM * HP;                                             \
        _Pragma("unroll")                                                       \
        for (int ni = 0; ni < 4; ni++)                                          \
            ldsm_x2(bfr[0][ni], smem_u32(&sB[(wn + ni * 8 + brow) * HP + bcol])); \
        _Pragma("unroll")                                                       \
        for (int mi = 0; mi < 4; mi++)                                          \
            ldsm_x4(afr[0][mi], smem_u32(&sA[(wm + mi * 16 + arow) * HP + acol])); \
        _Pragma("unroll")                                                       \
        for (int ksi = 0; ksi < 4; ksi++) {                                     \
            int cur = ksi & 1;                                                  \
            if (ksi < 3) {                                                      \
                int ks = (ksi + 1) * 16;                                        \
                _Pragma("unroll")                                               \
                for (int ni = 0; ni < 4; ni++)                                  \
                    ldsm_x2(bfr[cur ^ 1][ni],                                   \
                            smem_u32(&sB[(wn + ni * 8 + brow) * HP + ks + bcol])); \
                _Pragma("unroll")                                               \
                for (int mi = 0; mi < 4; mi++)                                  \
                    ldsm_x4(afr[cur ^ 1][mi],                                   \
                            smem_u32(&sA[(wm + mi * 16 + arow) * HP + ks + acol])); \
            }                                                                   \
            _Pragma("unroll")                                                   \
            for (int mi = 0; mi < 4; mi++)                                      \
                _Pragma("unroll")                                               \
                for (int ni = 0; ni < 4; ni++)                                  \
                    mma_f16(acc[mi][ni], afr[cur][mi], bfr[cur][ni]);           \
        }                                                                       \
        __syncthreads();                                                        \
        if (i + 2 < NC) issue(i + 2);                                           \
    }

// ---------------------------------------------------------------------------
// Fused QKV projection + RoPE + scale + fp16 hi/lo split.
//   n in [0,2048)     -> Qh/Ql (rope'd, scaled)
//   n in [2048,2560)  -> Kh/Kl (rope'd)
//   n in [2560,3072)  -> Vh
// ---------------------------------------------------------------------------
__device__ __forceinline__ uint32_t split_h(float x0, float x1, uint32_t& lo) {
    __half h0 = __float2half_rn(x0), h1 = __float2half_rn(x1);
    __half l0 = __float2half_rn(x0 - __half2float(h0));
    __half l1 = __float2half_rn(x1 - __half2float(h1));
    __half2 hp = {h0, h1}, lp = {l0, l1};
    lo = *(uint32_t*)&lp;
    return *(uint32_t*)&hp;
}

__global__ __launch_bounds__(256, 2) void gemm_qkv(
    const __half* __restrict__ A, const __half* __restrict__ W,
    __half* __restrict__ Qh, __half* __restrict__ Ql,
    __half* __restrict__ Kh, __half* __restrict__ Kl,
    __half* __restrict__ Vh,
    const float* __restrict__ fcos, const float* __restrict__ fsin)
{
    extern __shared__ __half sh[];
    GEMM_MAINLOOP(A, W, E_)

    #pragma unroll
    for (int mi = 0; mi < 4; mi++) {
        int r0 = bm + wm + mi * 16 + gid;
        int r1 = r0 + 8;
        #pragma unroll
        for (int ni = 0; ni < 4; ni++) {
            int n = bn + wn + ni * 8 + 2 * tig;
            float a0 = acc[mi][ni][0], a1 = acc[mi][ni][1];
            float a2 = acc[mi][ni][2], a3 = acc[mi][ni][3];
            if (n < E_) {                           // Q: rope + scale + split
                int jj = (n & 127) >> 1;
                float c0 = fcos[(r0 & (S_-1)) * 64 + jj];
                float s0 = fsin[(r0 & (S_-1)) * 64 + jj];
                float c1 = fcos[(r1 & (S_-1)) * 64 + jj];
                float s1 = fsin[(r1 & (S_-1)) * 64 + jj];
                float q0 = (a0 * c0 - a1 * s0) * SOFTMAX_SCALE;
                float q1 = (a0 * s0 + a1 * c0) * SOFTMAX_SCALE;
                float q2 = (a2 * c1 - a3 * s1) * SOFTMAX_SCALE;
                float q3 = (a2 * s1 + a3 * c1) * SOFTMAX_SCALE;
                uint32_t lo0, lo1;
                uint32_t hi0 = split_h(q0, q1, lo0);
                uint32_t hi1 = split_h(q2, q3, lo1);
                *(uint32_t*)&Qh[(size_t)r0 * E_ + n] = hi0;
                *(uint32_t*)&Ql[(size_t)r0 * E_ + n] = lo0;
                *(uint32_t*)&Qh[(size_t)r1 * E_ + n] = hi1;
                *(uint32_t*)&Ql[(size_t)r1 * E_ + n] = lo1;
            } else if (n < E_ + NKV_) {             // K: rope + split
                int nk = n - E_;
                int jj = (nk & 127) >> 1;
                float c0 = fcos[(r0 & (S_-1)) * 64 + jj];
                float s0 = fsin[(r0 & (S_-1)) * 64 + jj];
                float c1 = fcos[(r1 & (S_-1)) * 64 + jj];
                float s1 = fsin[(r1 & (S_-1)) * 64 + jj];
                float k0v = a0 * c0 - a1 * s0;
                float k1v = a0 * s0 + a1 * c0;
                float k2v = a2 * c1 - a3 * s1;
                float k3v = a2 * s1 + a3 * c1;
                uint32_t lo0, lo1;
                uint32_t hi0 = split_h(k0v, k1v, lo0);
                uint32_t hi1 = split_h(k2v, k3v, lo1);
                *(uint32_t*)&Kh[(size_t)r0 * NKV_ + nk] = hi0;
                *(uint32_t*)&Kl[(size_t)r0 * NKV_ + nk] = lo0;
                *(uint32_t*)&Kh[(size_t)r1 * NKV_ + nk] = hi1;
                *(uint32_t*)&Kl[(size_t)r1 * NKV_ + nk] = lo1;
            } else {                                // V: fp16
                int nv = n - E_ - NKV_;
                __half2 v0 = __floats2half2_rn(a0, a1);
                __half2 v1 = __floats2half2_rn(a2, a3);
                *(uint32_t*)&Vh[(size_t)r0 * NKV_ + nv] = *(uint32_t*)&v0;
                *(uint32_t*)&Vh[(size_t)r1 * NKV_ + nv] = *(uint32_t*)&v1;
            }
        }
    }
}

// ---------------------------------------------------------------------------
// Plain GEMM, fp32 out (o-proj).
// ---------------------------------------------------------------------------
__global__ __launch_bounds__(256, 2) void gemm_f32out(
    const __half* __restrict__ A, const __half* __restrict__ W,
    float* __restrict__ C, int M, int N, int K)
{
    extern __shared__ __half sh[];
    GEMM_MAINLOOP(A, W, K)

    #pragma unroll
    for (int mi = 0; mi < 4; mi++) {
        int r0 = bm + wm + mi * 16 + gid;
        #pragma unroll
        for (int ni = 0; ni < 4; ni++) {
            int col = bn + wn + ni * 8 + 2 * tig;
            *(float2*)&C[(size_t)r0 * N + col] =
                make_float2(acc[mi][ni][0], acc[mi][ni][1]);
            *(float2*)&C[(size_t)(r0 + 8) * N + col] =
                make_float2(acc[mi][ni][2], acc[mi][ni][3]);
        }
    }
}

// ===========================================================================
// fp16 flash attention — BM=128, 256 threads; fills are pure uint4 copies
// of pre-split fp16 operands.
// ===========================================================================
#define FBM 128
#define FBN 64
#define FQP 136
#define FPP 72
#define SQH_OFF 0
#define SQL_OFF (FBM * FQP)
#define SKH_OFF (2 * FBM * FQP)
#define SKL_OFF (SKH_OFF + FBN * FQP)
#define SPH_OFF (SKL_OFF + FBN * FQP)
#define FLASH_SMEM ((2 * FBM * FQP + 2 * FBN * FQP + 8 * 16 * FPP) * 2)  // 122880 B

__global__ __launch_bounds__(256) void flash_f16(
    const __half* __restrict__ Qh, const __half* __restrict__ Ql,
    const __half* __restrict__ Kh, const __half* __restrict__ Kl,
    const __half* __restrict__ Vh, __half* __restrict__ O)
{
    extern __shared__ __half fsm[];
    __half* sQh = fsm + SQH_OFF;
    __half* sQl = fsm + SQL_OFF;
    __half* sKh = fsm + SKH_OFF;
    __half* sKl = fsm + SKL_OFF;
    __half* sP  = fsm + SPH_OFF;
    __half* sV  = sKh;

    const int tid  = threadIdx.x;
    const int lane = tid & 31;
    const int warp = tid >> 5;
    const int gid  = lane >> 2;
    const int tig  = lane & 3;
    const int wrow = warp * 16;

    const int m_blk = blockIdx.x;
    const int bh    = blockIdx.y;
    const int b     = bh >> 4;
    const int h     = bh & 15;
    const int kvh   = h & 3;
    const int m0    = m_blk * FBM;

    __half* sPw = sP + warp * 16 * FPP;

    // ---- Q fill: straight copies (FBM rows x 16 uint4) -------------------
    for (int idx = tid; idx < FBM * 16; idx += 256) {
        int m = idx >> 4, d8 = (idx & 15) * 8;
        size_t g = ((size_t)(b * S_ + m0 + m) * H_ + h) * D_ + d8;
        *(uint4*)&sQh[m * FQP + d8] = *(const uint4*)&Qh[g];
        *(uint4*)&sQl[m * FQP + d8] = *(const uint4*)&Ql[g];
    }

    float row_m[2] = {-1e30f, -1e30f};
    float row_l[2] = {0.0f, 0.0f};
    float oacc[16][4];
    #pragma unroll
    for (int dt = 0; dt < 16; dt++)
        #pragma unroll
        for (int c = 0; c < 4; c++) oacc[dt][c] = 0.0f;

    const int NB = 2 * m_blk + 2;
    for (int nb = 0; nb < NB; nb++) {
        const int n0 = nb * FBN;
        __syncthreads();
        for (int idx = tid; idx < FBN * 16; idx += 256) {
            int n = idx >> 4, d8 = (idx & 15) * 8;
            size_t g = (size_t)(b * S_ + n0 + n) * NKV_ + kvh * D_ + d8;
            *(uint4*)&sKh[n * FQP + d8] = *(const uint4*)&Kh[g];
            *(uint4*)&sKl[n * FQP + d8] = *(const uint4*)&Kl[g];
        }
        __syncthreads();

        float sc[8][4];
        #pragma unroll
        for (int ni = 0; ni < 8; ni++)
            #pragma unroll
            for (int c = 0; c < 4; c++) sc[ni][c] = 0.0f;

        #pragma unroll
        for (int ks = 0; ks < D_; ks += 16) {
            uint32_t ah[4], al[4];
            ah[0] = *(uint32_t*)&sQh[(wrow + gid    ) * FQP + ks + 2 * tig    ];
            ah[1] = *(uint32_t*)&sQh[(wrow + gid + 8) * FQP + ks + 2 * tig    ];
            ah[2] = *(uint32_t*)&sQh[(wrow + gid    ) * FQP + ks + 2 * tig + 8];
            ah[3] = *(uint32_t*)&sQh[(wrow + gid + 8) * FQP + ks + 2 * tig + 8];
            al[0] = *(uint32_t*)&sQl[(wrow + gid    ) * FQP + ks + 2 * tig    ];
            al[1] = *(uint32_t*)&sQl[(wrow + gid + 8) * FQP + ks + 2 * tig    ];
            al[2] = *(uint32_t*)&sQl[(wrow + gid    ) * FQP + ks + 2 * tig + 8];
            al[3] = *(uint32_t*)&sQl[(wrow + gid + 8) * FQP + ks + 2 * tig + 8];
            #pragma unroll
            for (int ni = 0; ni < 8; ni++) {
                uint32_t bhf[2], blf[2];
                bhf[0] = *(uint32_t*)&sKh[(8 * ni + gid) * FQP + ks + 2 * tig    ];
                bhf[1] = *(uint32_t*)&sKh[(8 * ni + gid) * FQP + ks + 2 * tig + 8];
                blf[0] = *(uint32_t*)&sKl[(8 * ni + gid) * FQP + ks + 2 * tig    ];
                blf[1] = *(uint32_t*)&sKl[(8 * ni + gid) * FQP + ks + 2 * tig + 8];
                mma_f16(sc[ni], ah, bhf);
                mma_f16(sc[ni], al, bhf);
                mma_f16(sc[ni], ah, blf);
            }
        }

        if (n0 + FBN - 1 > m0 + wrow) {
            int r0g = m0 + wrow + gid, r1g = r0g + 8;
            #pragma unroll
            for (int ni = 0; ni < 8; ni++) {
                int c0g = n0 + 8 * ni + 2 * tig, c1g = c0g + 1;
                if (c0g > r0g) sc[ni][0] = -1e30f;
                if (c1g > r0g) sc[ni][1] = -1e30f;
                if (c0g > r1g) sc[ni][2] = -1e30f;
                if (c1g > r1g) sc[ni][3] = -1e30f;
            }
        }

        float mx0 = -1e30f, mx1 = -1e30f;
        #pragma unroll
        for (int ni = 0; ni < 8; ni++) {
            mx0 = fmaxf(mx0, fmaxf(sc[ni][0], sc[ni][1]));
            mx1 = fmaxf(mx1, fmaxf(sc[ni][2], sc[ni][3]));
        }
        #pragma unroll
        for (int off = 1; off <= 2; off <<= 1) {
            mx0 = fmaxf(mx0, __shfl_xor_sync(0xffffffffu, mx0, off));
            mx1 = fmaxf(mx1, __shfl_xor_sync(0xffffffffu, mx1, off));
        }
        float mn0 = fmaxf(row_m[0], mx0);
        float mn1 = fmaxf(row_m[1], mx1);
        float cr0 = __expf(row_m[0] - mn0);
        float cr1 = __expf(row_m[1] - mn1);
        row_m[0] = mn0; row_m[1] = mn1;

        float s0 = 0.0f, s1 = 0.0f;
        #pragma unroll
        for (int ni = 0; ni < 8; ni++) {
            float p0 = __expf(sc[ni][0] - mn0);
            float p1 = __expf(sc[ni][1] - mn0);
            float p2 = __expf(sc[ni][2] - mn1);
            float p3 = __expf(sc[ni][3] - mn1);
            s0 += p0 + p1; s1 += p2 + p3;
            int cc = 8 * ni + 2 * tig;
            __half2 pl = __floats2half2_rn(p0, p1);
            __half2 ph = __floats2half2_rn(p2, p3);
            *(uint32_t*)&sPw[ gid      * FPP + cc] = *(uint32_t*)&pl;
            *(uint32_t*)&sPw[(gid + 8) * FPP + cc] = *(uint32_t*)&ph;
        }
        #pragma unroll
        for (int off = 1; off <= 2; off <<= 1) {
            s0 += __shfl_xor_sync(0xffffffffu, s0, off);
            s1 += __shfl_xor_sync(0xffffffffu, s1, off);
        }
        row_l[0] = row_l[0] * cr0 + s0;
        row_l[1] = row_l[1] * cr1 + s1;
        #pragma unroll
        for (int dt = 0; dt < 16; dt++) {
            oacc[dt][0] *= cr0; oacc[dt][1] *= cr0;
            oacc[dt][2] *= cr1; oacc[dt][3] *= cr1;
        }

        __syncthreads();
        for (int idx = tid; idx < FBN * 16; idx += 256) {
            int n = idx >> 4, d8 = (idx & 15) * 8;
            size_t g = (size_t)(b * S_ + n0 + n) * NKV_ + kvh * D_ + d8;
            *(uint4*)&sV[n * FQP + d8] = *(const uint4*)&Vh[g];
        }
        __syncthreads();

        #pragma unroll
        for (int kb = 0; kb < FBN; kb += 16) {
            uint32_t pa[4];
            pa[0] = *(uint32_t*)&sPw[ gid      * FPP + kb + 2 * tig    ];
            pa[1] = *(uint32_t*)&sPw[(gid + 8) * FPP + kb + 2 * tig    ];
            pa[2] = *(uint32_t*)&sPw[ gid      * FPP + kb + 2 * tig + 8];
            pa[3] = *(uint32_t*)&sPw[(gid + 8) * FPP + kb + 2 * tig + 8];
            #pragma unroll
            for (int dt = 0; dt < 16; dt++) {
                uint32_t vb[2];
                ldsm_x2_trans(vb, smem_u32(&sV[(kb + (lane & 15)) * FQP + 8 * dt]));
                mma_f16(oacc[dt], pa, vb);
            }
        }
    }

    float inv0 = 1.0f / row_l[0];
    float inv1 = 1.0f / row_l[1];
    int r0 = b * S_ + m0 + wrow + gid;
    #pragma unroll
    for (int dt = 0; dt < 16; dt++) {
        int col = h * D_ + 8 * dt + 2 * tig;
        __half2 lo = __floats2half2_rn(oacc[dt][0] * inv0, oacc[dt][1] * inv0);
        __half2 hi = __floats2half2_rn(oacc[dt][2] * inv1, oacc[dt][3] * inv1);
        *(uint32_t*)&O[(size_t)r0 * E_ + col]       = *(uint32_t*)&lo;
        *(uint32_t*)&O[(size_t)(r0 + 8) * E_ + col] = *(uint32_t*)&hi;
    }
}

// ===========================================================================
extern "C" void kernel_launch(void* const* d_in, const int* in_sizes, int n_in,
                              void* d_out, int out_size)
{
    const float* x   = (const float*)d_in[0];
    const float* wq  = (const float*)d_in[1];
    const float* wk  = (const float*)d_in[2];
    const float* wv  = (const float*)d_in[3];
    const float* wo  = (const float*)d_in[4];
    const float* fco = (const float*)d_in[5];
    const float* fsi = (const float*)d_in[6];
    float* out = (float*)d_out;

    __half *Qhp, *Qlp, *Khp, *Klp, *Vhp, *xh, *wqkvh, *woh, *AOh;
    cudaGetSymbolAddress((void**)&Qhp,   g_Qh);
    cudaGetSymbolAddress((void**)&Qlp,   g_Ql);
    cudaGetSymbolAddress((void**)&Khp,   g_Kh);
    cudaGetSymbolAddress((void**)&Klp,   g_Kl);
    cudaGetSymbolAddress((void**)&Vhp,   g_Vh);
    cudaGetSymbolAddress((void**)&xh,    g_xh);
    cudaGetSymbolAddress((void**)&wqkvh, g_wqkvh);
    cudaGetSymbolAddress((void**)&woh,   g_woh);
    cudaGetSymbolAddress((void**)&AOh,   g_AOh);

    cudaFuncSetAttribute(flash_f16, cudaFuncAttributeMaxDynamicSharedMemorySize,
                         FLASH_SMEM);
    cudaFuncSetAttribute(gemm_qkv, cudaFuncAttributeMaxDynamicSharedMemorySize,
                         GEMM_SMEM);
    cudaFuncSetAttribute(gemm_f32out, cudaFuncAttributeMaxDynamicSharedMemorySize,
                         GEMM_SMEM);

    // idx 0-2: conversions
    cvt_f32_f16<<<(BS_ * E_ / 8 + 255) / 256, 256>>>(x, xh, BS_ * E_);
    cvt3_f32_f16<<<(NQKV_ * E_ / 8 + 255) / 256, 256>>>(wq, wk, wv, wqkvh);
    cvt_f32_f16<<<(E_ * E_ / 8 + 255) / 256, 256>>>(wo, woh, E_ * E_);

    // idx 3 (ncu-profiled): fused QKV projection + RoPE + fp16 split
    gemm_qkv<<<dim3(NQKV_ / TBN, BS_ / TBM), 256, GEMM_SMEM>>>(
        xh, wqkvh, Qhp, Qlp, Khp, Klp, Vhp, fco, fsi);

    // idx 4: flash attention -> fp16 AO
    flash_f16<<<dim3(S_ / FBM, B_ * H_), 256, FLASH_SMEM>>>(
        Qhp, Qlp, Khp, Klp, Vhp, AOh);

    // idx 5: output projection
    gemm_f32out<<<dim3(E_ / TBN, BS_ / TBM), 256, GEMM_SMEM>>>(
        AOh, woh, out, BS_, E_, E_);
}